// round 1
// baseline (speedup 1.0000x reference)
#include <cuda_runtime.h>
#include <math.h>

// Problem constants (from reference): H=1024, B=1024, S=128 (T=127), E=6, V=3, C=10
#define HD   1024
#define BD   1024
#define SD   128
#define TD   127
#define ED   6
#define VD   3
#define CD   10

// Scratch state in static device memory (no allocations allowed).
__device__ float g_pre[4u * HD * BD];   // gate preactivations [gate][h][b], 16 MB
__device__ float g_h[HD * BD];          // hidden state [h][b], 4 MB
__device__ float g_c[HD * BD];          // cell state   [h][b], 4 MB
__device__ float g_Q[4 * VD * HD];      // per-token input contribution + bias [gate][v][h]

// ---------------------------------------------------------------------------
// Copy initial state into device globals (graph-capturable, deterministic).
__global__ void init_state(const float* __restrict__ h0, const float* __restrict__ c0) {
    int i = blockIdx.x * blockDim.x + threadIdx.x;
    if (i < HD * BD) { g_h[i] = h0[i]; g_c[i] = c0[i]; }
}

// ---------------------------------------------------------------------------
// Q[gate][v][h] = b_gate[h] + sum_e W_gate_x[h][e] * emb[v][e]
// (V=3, E=6: the entire input path collapses to this tiny table.)
__global__ void build_Q(const float* __restrict__ emb,
                        const float* __restrict__ Wgx, const float* __restrict__ bg,
                        const float* __restrict__ Wix, const float* __restrict__ bi,
                        const float* __restrict__ Wfx, const float* __restrict__ bf,
                        const float* __restrict__ Wox, const float* __restrict__ bo) {
    int i = blockIdx.x * blockDim.x + threadIdx.x;
    if (i >= 4 * VD * HD) return;
    int gate = i / (VD * HD);
    int r = i % (VD * HD);
    int v = r >> 10;
    int h = r & (HD - 1);
    const float* Wx = (gate == 0) ? Wgx : (gate == 1) ? Wix : (gate == 2) ? Wfx : Wox;
    const float* bb = (gate == 0) ? bg  : (gate == 1) ? bi  : (gate == 2) ? bf  : bo;
    float s = bb[h];
#pragma unroll
    for (int e = 0; e < ED; e++) s += Wx[h * ED + e] * emb[v * ED + e];
    g_Q[i] = s;
}

// ---------------------------------------------------------------------------
// Per-step fused 4-gate GEMM: pre[gate][h][b] = Q[gate][x[b,t]][h]
//                                              + sum_k W_gate_h[h][k] * g_h[k][b]
// Classic 128x128x8 SGEMM tile, 256 threads, 8x8 per thread.
// Grid: x = B/128 (=8), y = 4*H/128 (=32).  Each y-block lies inside one gate.
__global__ __launch_bounds__(256)
void gate_gemm(const float* __restrict__ W0, const float* __restrict__ W1,
               const float* __restrict__ W2, const float* __restrict__ W3,
               const int* __restrict__ x, int t) {
    __shared__ float As[8][128];   // A tile transposed: As[k][m]
    __shared__ float Bs[8][128];   // B tile: Bs[k][n]

    const int tid = threadIdx.x;
    const int tx = tid & 15;        // n-sub (0..15)
    const int ty = tid >> 4;        // m-sub (0..15)
    const int nb = blockIdx.x * 128;          // batch column base
    const int gate = blockIdx.y >> 3;         // 128 rows per block, 8 blocks per gate
    const int hb = (blockIdx.y & 7) * 128;    // h row base within the gate

    const float* __restrict__ W =
        (gate == 0) ? W0 : (gate == 1) ? W1 : (gate == 2) ? W2 : W3;

    float acc[8][8];
#pragma unroll
    for (int i = 0; i < 8; i++)
#pragma unroll
        for (int j = 0; j < 8; j++) acc[i][j] = 0.0f;

    const int a_row = tid >> 1;            // 0..127
    const int a_col = (tid & 1) * 4;       // 0 or 4
    const int b_row = tid >> 5;            // 0..7
    const int b_col = (tid & 31) * 4;      // 0..124

    for (int k0 = 0; k0 < HD; k0 += 8) {
        // Load A tile (W rows [hb, hb+128), k cols [k0, k0+8)) transposed into As.
        float4 av = *reinterpret_cast<const float4*>(&W[(size_t)(hb + a_row) * HD + k0 + a_col]);
        As[a_col + 0][a_row] = av.x;
        As[a_col + 1][a_row] = av.y;
        As[a_col + 2][a_row] = av.z;
        As[a_col + 3][a_row] = av.w;
        // Load B tile (g_h rows [k0,k0+8), cols [nb, nb+128)).
        float4 bv = *reinterpret_cast<const float4*>(&g_h[(size_t)(k0 + b_row) * BD + nb + b_col]);
        *reinterpret_cast<float4*>(&Bs[b_row][b_col]) = bv;
        __syncthreads();

#pragma unroll
        for (int k = 0; k < 8; k++) {
            float a[8], b[8];
            *reinterpret_cast<float4*>(&a[0]) = *reinterpret_cast<const float4*>(&As[k][ty * 8]);
            *reinterpret_cast<float4*>(&a[4]) = *reinterpret_cast<const float4*>(&As[k][ty * 8 + 4]);
            *reinterpret_cast<float4*>(&b[0]) = *reinterpret_cast<const float4*>(&Bs[k][tx * 8]);
            *reinterpret_cast<float4*>(&b[4]) = *reinterpret_cast<const float4*>(&Bs[k][tx * 8 + 4]);
#pragma unroll
            for (int i = 0; i < 8; i++)
#pragma unroll
                for (int j = 0; j < 8; j++) acc[i][j] = fmaf(a[i], b[j], acc[i][j]);
        }
        __syncthreads();
    }

    // Epilogue: add per-token input contribution + bias, store preactivations.
    int vtok[8];
#pragma unroll
    for (int j = 0; j < 8; j++) vtok[j] = x[(size_t)(nb + tx * 8 + j) * SD + t];

    float* __restrict__ preg = &g_pre[(size_t)gate * HD * BD];
    const float* __restrict__ Qg = &g_Q[gate * VD * HD];
#pragma unroll
    for (int i = 0; i < 8; i++) {
        int h = hb + ty * 8 + i;
#pragma unroll
        for (int j = 0; j < 8; j++) {
            int b = nb + tx * 8 + j;
            preg[(size_t)h * BD + b] = acc[i][j] + Qg[vtok[j] * HD + h];
        }
    }
}

// ---------------------------------------------------------------------------
// Elementwise LSTM cell update: consumes the 4 preactivation planes.
__global__ void cell_update() {
    int i = blockIdx.x * blockDim.x + threadIdx.x;   // i = h*B + b, coalesced over b
    float pg = g_pre[i];
    float pi = g_pre[1u * HD * BD + i];
    float pf = g_pre[2u * HD * BD + i];
    float po = g_pre[3u * HD * BD + i];
    float g  = tanhf(pg);
    float ig = 1.0f / (1.0f + expf(-pi));
    float fg = 1.0f / (1.0f + expf(-pf));
    float og = 1.0f / (1.0f + expf(-po));
    float c2 = g * ig + g_c[i] * fg;
    g_c[i] = c2;
    g_h[i] = tanhf(c2) * og;
}

// ---------------------------------------------------------------------------
// Final projection p = W_ph @ h + b_p  (C=10), then log_softmax over C per batch.
// One thread per batch column; W_ph broadcasts through the cache.
__global__ void proj_logsoftmax(const float* __restrict__ Wph,
                                const float* __restrict__ bp,
                                float* __restrict__ out) {
    int b = blockIdx.x * blockDim.x + threadIdx.x;
    if (b >= BD) return;
    float acc[CD];
#pragma unroll
    for (int c = 0; c < CD; c++) acc[c] = bp[c];
    for (int k = 0; k < HD; k++) {
        float hv = g_h[(size_t)k * BD + b];
#pragma unroll
        for (int c = 0; c < CD; c++) acc[c] = fmaf(Wph[c * HD + k], hv, acc[c]);
    }
    float m = acc[0];
#pragma unroll
    for (int c = 1; c < CD; c++) m = fmaxf(m, acc[c]);
    float s = 0.0f;
#pragma unroll
    for (int c = 0; c < CD; c++) s += expf(acc[c] - m);
    float lse = m + logf(s);
#pragma unroll
    for (int c = 0; c < CD; c++) out[b * CD + c] = acc[c] - lse;
}

// ---------------------------------------------------------------------------
extern "C" void kernel_launch(void* const* d_in, const int* in_sizes, int n_in,
                              void* d_out, int out_size) {
    const int*   x    = (const int*)  d_in[0];
    const float* emb  = (const float*)d_in[1];
    const float* W_gx = (const float*)d_in[2];
    const float* W_gh = (const float*)d_in[3];
    const float* b_g  = (const float*)d_in[4];
    const float* W_ix = (const float*)d_in[5];
    const float* W_ih = (const float*)d_in[6];
    const float* b_i  = (const float*)d_in[7];
    const float* W_fx = (const float*)d_in[8];
    const float* W_fh = (const float*)d_in[9];
    const float* b_f  = (const float*)d_in[10];
    const float* W_ox = (const float*)d_in[11];
    const float* W_oh = (const float*)d_in[12];
    const float* b_o  = (const float*)d_in[13];
    const float* W_ph = (const float*)d_in[14];
    const float* b_p  = (const float*)d_in[15];
    const float* h0   = (const float*)d_in[16];
    const float* c0   = (const float*)d_in[17];
    float* out = (float*)d_out;

    init_state<<<(HD * BD + 255) / 256, 256>>>(h0, c0);
    build_Q<<<(4 * VD * HD + 255) / 256, 256>>>(emb, W_gx, b_g, W_ix, b_i,
                                                W_fx, b_f, W_ox, b_o);

    dim3 grid(BD / 128, (4 * HD) / 128);   // (8, 32)
    for (int t = 0; t < TD; t++) {
        gate_gemm<<<grid, 256>>>(W_gh, W_ih, W_fh, W_oh, x, t);
        cell_update<<<(HD * BD) / 256, 256>>>();
    }
    proj_logsoftmax<<<(BD + 255) / 256, 256>>>(W_ph, b_p, out);
}

// round 2
// speedup vs baseline: 3.1768x; 3.1768x over previous
#include <cuda_runtime.h>
#include <math.h>
#include <stdint.h>

// Problem constants: H=1024, B=1024, S=128 (T=127), E=6, V=3, C=10
#define HD   1024
#define BD   1024
#define SD   128
#define TD   127
#define ED   6
#define VD   3
#define CD   10

// Scratch state in static device memory (no allocations allowed).
__device__ float g_pre[4u * HD * BD];   // gate preactivations [gate][h][b], 16 MB
__device__ float g_h[HD * BD];          // hidden state [h][b], 4 MB
__device__ float g_c[HD * BD];          // cell state   [h][b], 4 MB
__device__ float g_Q[4 * VD * HD];      // per-token input contribution + bias [gate][v][h]

// ---------------------------------------------------------------------------
__device__ __forceinline__ uint32_t f2tf32(float x) {
    uint32_t r;
    asm("cvt.rna.tf32.f32 %0, %1;" : "=r"(r) : "f"(x));
    return r;
}

__device__ __forceinline__ void mma_tf32(float c[4], const uint32_t a[4], const uint32_t b[2]) {
    asm volatile(
        "mma.sync.aligned.m16n8k8.row.col.f32.tf32.tf32.f32 "
        "{%0,%1,%2,%3}, {%4,%5,%6,%7}, {%8,%9}, {%0,%1,%2,%3};"
        : "+f"(c[0]), "+f"(c[1]), "+f"(c[2]), "+f"(c[3])
        : "r"(a[0]), "r"(a[1]), "r"(a[2]), "r"(a[3]), "r"(b[0]), "r"(b[1]));
}

// ---------------------------------------------------------------------------
__global__ void init_state(const float* __restrict__ h0, const float* __restrict__ c0) {
    int i = blockIdx.x * blockDim.x + threadIdx.x;
    if (i < HD * BD) { g_h[i] = h0[i]; g_c[i] = c0[i]; }
}

// Q[gate][v][h] = b_gate[h] + sum_e W_gate_x[h][e] * emb[v][e]
__global__ void build_Q(const float* __restrict__ emb,
                        const float* __restrict__ Wgx, const float* __restrict__ bg,
                        const float* __restrict__ Wix, const float* __restrict__ bi,
                        const float* __restrict__ Wfx, const float* __restrict__ bf,
                        const float* __restrict__ Wox, const float* __restrict__ bo) {
    int i = blockIdx.x * blockDim.x + threadIdx.x;
    if (i >= 4 * VD * HD) return;
    int gate = i / (VD * HD);
    int r = i % (VD * HD);
    int v = r >> 10;
    int h = r & (HD - 1);
    const float* Wx = (gate == 0) ? Wgx : (gate == 1) ? Wix : (gate == 2) ? Wfx : Wox;
    const float* bb = (gate == 0) ? bg  : (gate == 1) ? bi  : (gate == 2) ? bf  : bo;
    float s = bb[h];
#pragma unroll
    for (int e = 0; e < ED; e++) s += Wx[h * ED + e] * emb[v * ED + e];
    g_Q[i] = s;
}

// ---------------------------------------------------------------------------
// tf32 tensor-core gate GEMM: pre[gate][h][b] = Q[gate][x[b,t]][h]
//                                             + sum_k W_gate_h[h][k] * g_h[k][b]
// Block tile 128x128, BK=32, 8 warps (2x4), warp tile 64x32 = 4x4 m16n8k8 frags.
// Grid: x = B/128 (=8), y = 4*H/128 (=32).
__global__ __launch_bounds__(256, 2)
void gate_gemm_tf32(const float* __restrict__ W0, const float* __restrict__ W1,
                    const float* __restrict__ W2, const float* __restrict__ W3,
                    const int* __restrict__ x, int t) {
    __shared__ uint32_t As[128][36];    // A tile [m][k], stride 36 -> frag loads conflict-free
    __shared__ uint32_t Bs[32][136];    // B tile [k][n], stride 136 -> frag loads conflict-free

    const int tid  = threadIdx.x;
    const int warp = tid >> 5;
    const int lane = tid & 31;
    const int wm = warp >> 2;            // 0..1  -> m offset wm*64
    const int wn = warp & 3;             // 0..3  -> n offset wn*32
    const int qrow = lane >> 2;          // 0..7
    const int qcol = lane & 3;           // 0..3

    const int nb   = blockIdx.x * 128;
    const int gate = blockIdx.y >> 3;
    const int hb   = (blockIdx.y & 7) * 128;

    const float* __restrict__ W =
        (gate == 0) ? W0 : (gate == 1) ? W1 : (gate == 2) ? W2 : W3;

    float acc[4][4][4];
#pragma unroll
    for (int i = 0; i < 4; i++)
#pragma unroll
        for (int j = 0; j < 4; j++)
#pragma unroll
            for (int k = 0; k < 4; k++) acc[i][j][k] = 0.0f;

    const int ar  = tid >> 3;            // 0..31, A row group
    const int ac4 = (tid & 7) * 4;       // A col (k) base, 0..28
    const int br  = tid >> 5;            // 0..7,  B row group
    const int bc4 = (tid & 31) * 4;      // B col base, 0..124

    for (int k0 = 0; k0 < HD; k0 += 32) {
        // Fill A tile: W rows [hb,hb+128), k cols [k0,k0+32), tf32-rounded.
#pragma unroll
        for (int r = 0; r < 4; r++) {
            int m = ar + r * 32;
            float4 v = *reinterpret_cast<const float4*>(&W[(size_t)(hb + m) * HD + k0 + ac4]);
            As[m][ac4 + 0] = f2tf32(v.x);
            As[m][ac4 + 1] = f2tf32(v.y);
            As[m][ac4 + 2] = f2tf32(v.z);
            As[m][ac4 + 3] = f2tf32(v.w);
        }
        // Fill B tile: g_h rows [k0,k0+32), cols [nb,nb+128), tf32-rounded.
#pragma unroll
        for (int r = 0; r < 4; r++) {
            int k = br + r * 8;
            float4 v = *reinterpret_cast<const float4*>(&g_h[(size_t)(k0 + k) * BD + nb + bc4]);
            Bs[k][bc4 + 0] = f2tf32(v.x);
            Bs[k][bc4 + 1] = f2tf32(v.y);
            Bs[k][bc4 + 2] = f2tf32(v.z);
            Bs[k][bc4 + 3] = f2tf32(v.w);
        }
        __syncthreads();

#pragma unroll
        for (int sub = 0; sub < 4; sub++) {
            const int ks = sub * 8;
            uint32_t af[4][4];
#pragma unroll
            for (int mf = 0; mf < 4; mf++) {
                int m = wm * 64 + mf * 16 + qrow;
                af[mf][0] = As[m][ks + qcol];
                af[mf][1] = As[m + 8][ks + qcol];
                af[mf][2] = As[m][ks + qcol + 4];
                af[mf][3] = As[m + 8][ks + qcol + 4];
            }
            uint32_t bf[4][2];
#pragma unroll
            for (int nf = 0; nf < 4; nf++) {
                int n = wn * 32 + nf * 8 + qrow;
                bf[nf][0] = Bs[ks + qcol][n];
                bf[nf][1] = Bs[ks + qcol + 4][n];
            }
#pragma unroll
            for (int mf = 0; mf < 4; mf++)
#pragma unroll
                for (int nf = 0; nf < 4; nf++)
                    mma_tf32(acc[mf][nf], af[mf], bf[nf]);
        }
        __syncthreads();
    }

    // Epilogue: add token-dependent input contribution + bias; store preactivations.
    int vtok[4][2];
#pragma unroll
    for (int nf = 0; nf < 4; nf++) {
        int b0 = nb + wn * 32 + nf * 8 + qcol * 2;
        vtok[nf][0] = x[(size_t)b0 * SD + t];
        vtok[nf][1] = x[(size_t)(b0 + 1) * SD + t];
    }

    float* __restrict__ preg = &g_pre[(size_t)gate * HD * BD];
    const float* __restrict__ Qg = &g_Q[gate * VD * HD];
#pragma unroll
    for (int mf = 0; mf < 4; mf++) {
        int h0 = hb + wm * 64 + mf * 16 + qrow;
        int h1 = h0 + 8;
#pragma unroll
        for (int nf = 0; nf < 4; nf++) {
            int b0 = nb + wn * 32 + nf * 8 + qcol * 2;
            float2 r0, r1;
            r0.x = acc[mf][nf][0] + Qg[vtok[nf][0] * HD + h0];
            r0.y = acc[mf][nf][1] + Qg[vtok[nf][1] * HD + h0];
            r1.x = acc[mf][nf][2] + Qg[vtok[nf][0] * HD + h1];
            r1.y = acc[mf][nf][3] + Qg[vtok[nf][1] * HD + h1];
            *reinterpret_cast<float2*>(&preg[(size_t)h0 * BD + b0]) = r0;
            *reinterpret_cast<float2*>(&preg[(size_t)h1 * BD + b0]) = r1;
        }
    }
}

// ---------------------------------------------------------------------------
// Elementwise LSTM cell update, float4 vectorized.
__device__ __forceinline__ float sigm(float v) { return 1.0f / (1.0f + __expf(-v)); }

__global__ void cell_update() {
    int i = (blockIdx.x * blockDim.x + threadIdx.x) * 4;
    float4 pg = *reinterpret_cast<const float4*>(&g_pre[i]);
    float4 pi = *reinterpret_cast<const float4*>(&g_pre[1u * HD * BD + i]);
    float4 pf = *reinterpret_cast<const float4*>(&g_pre[2u * HD * BD + i]);
    float4 po = *reinterpret_cast<const float4*>(&g_pre[3u * HD * BD + i]);
    float4 cc = *reinterpret_cast<const float4*>(&g_c[i]);
    float4 c2, h2;
    c2.x = tanhf(pg.x) * sigm(pi.x) + cc.x * sigm(pf.x);
    c2.y = tanhf(pg.y) * sigm(pi.y) + cc.y * sigm(pf.y);
    c2.z = tanhf(pg.z) * sigm(pi.z) + cc.z * sigm(pf.z);
    c2.w = tanhf(pg.w) * sigm(pi.w) + cc.w * sigm(pf.w);
    h2.x = tanhf(c2.x) * sigm(po.x);
    h2.y = tanhf(c2.y) * sigm(po.y);
    h2.z = tanhf(c2.z) * sigm(po.z);
    h2.w = tanhf(c2.w) * sigm(po.w);
    *reinterpret_cast<float4*>(&g_c[i]) = c2;
    *reinterpret_cast<float4*>(&g_h[i]) = h2;
}

// ---------------------------------------------------------------------------
// Final projection p = W_ph @ h + b_p (C=10), then log_softmax per batch column.
__global__ void proj_logsoftmax(const float* __restrict__ Wph,
                                const float* __restrict__ bp,
                                float* __restrict__ out) {
    int b = blockIdx.x * blockDim.x + threadIdx.x;
    if (b >= BD) return;
    float acc[CD];
#pragma unroll
    for (int c = 0; c < CD; c++) acc[c] = bp[c];
    for (int k = 0; k < HD; k++) {
        float hv = g_h[(size_t)k * BD + b];
#pragma unroll
        for (int c = 0; c < CD; c++) acc[c] = fmaf(Wph[c * HD + k], hv, acc[c]);
    }
    float m = acc[0];
#pragma unroll
    for (int c = 1; c < CD; c++) m = fmaxf(m, acc[c]);
    float s = 0.0f;
#pragma unroll
    for (int c = 0; c < CD; c++) s += expf(acc[c] - m);
    float lse = m + logf(s);
#pragma unroll
    for (int c = 0; c < CD; c++) out[b * CD + c] = acc[c] - lse;
}

// ---------------------------------------------------------------------------
extern "C" void kernel_launch(void* const* d_in, const int* in_sizes, int n_in,
                              void* d_out, int out_size) {
    const int*   x    = (const int*)  d_in[0];
    const float* emb  = (const float*)d_in[1];
    const float* W_gx = (const float*)d_in[2];
    const float* W_gh = (const float*)d_in[3];
    const float* b_g  = (const float*)d_in[4];
    const float* W_ix = (const float*)d_in[5];
    const float* W_ih = (const float*)d_in[6];
    const float* b_i  = (const float*)d_in[7];
    const float* W_fx = (const float*)d_in[8];
    const float* W_fh = (const float*)d_in[9];
    const float* b_f  = (const float*)d_in[10];
    const float* W_ox = (const float*)d_in[11];
    const float* W_oh = (const float*)d_in[12];
    const float* b_o  = (const float*)d_in[13];
    const float* W_ph = (const float*)d_in[14];
    const float* b_p  = (const float*)d_in[15];
    const float* h0   = (const float*)d_in[16];
    const float* c0   = (const float*)d_in[17];
    float* out = (float*)d_out;

    init_state<<<(HD * BD + 255) / 256, 256>>>(h0, c0);
    build_Q<<<(4 * VD * HD + 255) / 256, 256>>>(emb, W_gx, b_g, W_ix, b_i,
                                                W_fx, b_f, W_ox, b_o);

    dim3 grid(BD / 128, (4 * HD) / 128);   // (8, 32)
    for (int t = 0; t < TD; t++) {
        gate_gemm_tf32<<<grid, 256>>>(W_gh, W_ih, W_fh, W_oh, x, t);
        cell_update<<<(HD * BD) / (256 * 4), 256>>>();
    }
    proj_logsoftmax<<<(BD + 255) / 256, 256>>>(W_ph, b_p, out);
}

// round 4
// speedup vs baseline: 6.7109x; 2.1125x over previous
#include <cuda_runtime.h>
#include <cuda_bf16.h>
#include <math.h>
#include <stdint.h>

// Problem constants: H=1024, B=1024, S=128 (T=127), E=6, V=3, C=10
#define HD   1024
#define BD   1024
#define SD   128
#define TD   127
#define ED   6
#define VD   3
#define CD   10

#define NB   128      // batch cols per block
#define BK   64       // k per chunk
#define NCH  (HD/BK)  // 16 chunks

// ---------------------------------------------------------------------------
// Static device scratch (no allocations allowed).
__device__ __nv_bfloat16 g_Wr[32u * 128 * HD];  // rearranged weights: [hblk][gate*32+hl][k]
__device__ __nv_bfloat16 g_hT[BD * HD];         // h transposed bf16 [b][h] (B operand)
__device__ float         g_c[HD * BD];          // cell state [h][b]
__device__ float         g_Q[4 * VD * HD];      // input contribution + bias [gate][v][h]

// ---------------------------------------------------------------------------
__device__ __forceinline__ uint32_t smem_u32(const void* p) {
    uint32_t a;
    asm("{ .reg .u64 t; cvta.to.shared.u64 t, %1; cvt.u32.u64 %0, t; }" : "=r"(a) : "l"(p));
    return a;
}

__device__ __forceinline__ void cp16(uint32_t dst, const void* src) {
    asm volatile("cp.async.cg.shared.global [%0], [%1], 16;" :: "r"(dst), "l"(src));
}
__device__ __forceinline__ void cp_commit() {
    asm volatile("cp.async.commit_group;" ::: "memory");
}
template <int N> __device__ __forceinline__ void cp_wait() {
    asm volatile("cp.async.wait_group %0;" :: "n"(N) : "memory");
}

__device__ __forceinline__ void ldm_x4(uint32_t r[4], uint32_t addr) {
    asm volatile("ldmatrix.sync.aligned.m8n8.x4.shared.b16 {%0,%1,%2,%3}, [%4];"
                 : "=r"(r[0]), "=r"(r[1]), "=r"(r[2]), "=r"(r[3]) : "r"(addr));
}

__device__ __forceinline__ void mma_bf16(float c[4], const uint32_t a[4],
                                         const uint32_t b0, const uint32_t b1) {
    asm volatile(
        "mma.sync.aligned.m16n8k16.row.col.f32.bf16.bf16.f32 "
        "{%0,%1,%2,%3}, {%4,%5,%6,%7}, {%8,%9}, {%0,%1,%2,%3};"
        : "+f"(c[0]), "+f"(c[1]), "+f"(c[2]), "+f"(c[3])
        : "r"(a[0]), "r"(a[1]), "r"(a[2]), "r"(a[3]), "r"(b0), "r"(b1));
}

__device__ __forceinline__ float sigm(float v) { return 1.0f / (1.0f + __expf(-v)); }
__device__ __forceinline__ float qsel(float a, float b, float c, int t) {
    return t == 0 ? a : (t == 1 ? b : c);
}

// Swizzled byte offset inside a 128B-row tile: (r, c16) with c16 in [0,8)
__device__ __forceinline__ uint32_t SW(int r, int c16) {
    return (uint32_t)(r * 128) + ((uint32_t)(c16 << 4) ^ (uint32_t)((r & 7) << 4));
}

// ---------------------------------------------------------------------------
// One-time init kernels
__global__ void init_state(const float* __restrict__ h0, const float* __restrict__ c0) {
    int i = blockIdx.x * blockDim.x + threadIdx.x;
    if (i < HD * BD) {
        g_c[i] = c0[i];
        int h = i >> 10, b = i & (BD - 1);
        g_hT[(size_t)b * HD + h] = __float2bfloat16(h0[i]);
    }
}

// Rearranged bf16 weights: g_Wr[((y*128 + gate*32 + hl))*HD + k] = W_gate[(y*32+hl)*HD + k]
__global__ void prep_weights(const float* __restrict__ W0, const float* __restrict__ W1,
                             const float* __restrict__ W2, const float* __restrict__ W3) {
    size_t e = (size_t)(blockIdx.x * blockDim.x + threadIdx.x) * 4;
    if (e >= 32ull * 128 * HD) return;
    int k = (int)(e & (HD - 1));
    int r = (int)((e >> 10) & 127);
    int y = (int)(e >> 17);
    int gate = r >> 5;
    int h = y * 32 + (r & 31);
    const float* W = gate == 0 ? W0 : gate == 1 ? W1 : gate == 2 ? W2 : W3;
    float4 v = *reinterpret_cast<const float4*>(&W[(size_t)h * HD + k]);
    *reinterpret_cast<__nv_bfloat162*>(&g_Wr[e])     = __floats2bfloat162_rn(v.x, v.y);
    *reinterpret_cast<__nv_bfloat162*>(&g_Wr[e + 2]) = __floats2bfloat162_rn(v.z, v.w);
}

__global__ void build_Q(const float* __restrict__ emb,
                        const float* __restrict__ Wgx, const float* __restrict__ bg,
                        const float* __restrict__ Wix, const float* __restrict__ bi,
                        const float* __restrict__ Wfx, const float* __restrict__ bf,
                        const float* __restrict__ Wox, const float* __restrict__ bo) {
    int i = blockIdx.x * blockDim.x + threadIdx.x;
    if (i >= 4 * VD * HD) return;
    int gate = i / (VD * HD);
    int r = i % (VD * HD);
    int v = r >> 10;
    int h = r & (HD - 1);
    const float* Wx = (gate == 0) ? Wgx : (gate == 1) ? Wix : (gate == 2) ? Wfx : Wox;
    const float* bb = (gate == 0) ? bg  : (gate == 1) ? bi  : (gate == 2) ? bf  : bo;
    float s = bb[h];
#pragma unroll
    for (int e = 0; e < ED; e++) s += Wx[h * ED + e] * emb[v * ED + e];
    g_Q[i] = s;
}

// ---------------------------------------------------------------------------
// Fully fused LSTM step: 4-gate GEMM (bf16 mma.sync) + cell update + transpose.
// Block: m=128 (4 gates x 32 h), n=128 (batch), K=1024.
// Grid: (B/128=8, H/32=32). 256 threads = 8 warps (4 m-groups x 2 n-halves).
// SMEM: mainloop 2 stages x (A 16KB + B 16KB) = 64KB, then reused as
//       spre[4][32][132] f32 (67.6KB) + shT[128][34] bf16 (8.7KB).
#define SMEM_STEP (4 * 32 * 132 * 4 + 128 * 34 * 2)

__global__ __launch_bounds__(256, 2) void lstm_step(const int* __restrict__ x, int t) {
    extern __shared__ char smem[];
    const uint32_t sb = smem_u32(smem);
    const int tid = threadIdx.x;
    const int lane = tid & 31;
    const int warp = tid >> 5;
    const int m0 = (warp >> 1) * 32;    // also: gate = warp>>1
    const int n0 = (warp & 1) * 64;
    const int b0 = blockIdx.x * NB;
    const int hblk = blockIdx.y;

    const __nv_bfloat16* __restrict__ Wblk = &g_Wr[(size_t)hblk * 128 * HD];
    const __nv_bfloat16* __restrict__ Bsrc = &g_hT[(size_t)b0 * HD];

    // cp.async staging: per-thread 4 A units + 4 B units of 16B per stage.
    const int ur = tid >> 3;          // rows ur, ur+32, ur+64, ur+96
    const int uc = tid & 7;           // 16B column
    const uint32_t sw_off = SW(ur, uc);  // row/col base; +32 rows adds 32*128 bytes, XOR unchanged (r&7 same)

#pragma unroll
    for (int j = 0; j < 4; j++) {     // stage 0 prefetch
        uint32_t d = sb + sw_off + j * (32 * 128);
        cp16(d,          &Wblk[(size_t)(ur + j * 32) * HD + uc * 8]);
        cp16(d + 16384,  &Bsrc[(size_t)(ur + j * 32) * HD + uc * 8]);
    }
    cp_commit();

    float acc[2][8][4];
#pragma unroll
    for (int i = 0; i < 2; i++)
#pragma unroll
        for (int j = 0; j < 8; j++)
#pragma unroll
            for (int k = 0; k < 4; k++) acc[i][j][k] = 0.0f;

    // ldmatrix per-lane address components
    const int a_r = m0 + (lane & 15);
    const int a_cadd = lane >> 4;                       // +0/+1 c16
    const int b_radd = (lane & 7) + ((lane & 16) >> 1); // row within 16-row pair group
    const int b_cadd = (lane >> 3) & 1;

#pragma unroll 1
    for (int ch = 0; ch < NCH; ch++) {
        if (ch + 1 < NCH) {
            const int s2 = (ch + 1) & 1;
            const int koff = (ch + 1) * BK;
#pragma unroll
            for (int j = 0; j < 4; j++) {
                uint32_t d = sb + s2 * 32768 + sw_off + j * (32 * 128);
                cp16(d,         &Wblk[(size_t)(ur + j * 32) * HD + koff + uc * 8]);
                cp16(d + 16384, &Bsrc[(size_t)(ur + j * 32) * HD + koff + uc * 8]);
            }
            cp_commit();
            cp_wait<1>();
        } else {
            cp_wait<0>();
        }
        __syncthreads();

        const uint32_t Ab = sb + (ch & 1) * 32768;
        const uint32_t Bb = Ab + 16384;
#pragma unroll
        for (int ks = 0; ks < 4; ks++) {
            const int c16 = ks * 2;
            uint32_t a[2][4];
#pragma unroll
            for (int mf = 0; mf < 2; mf++)
                ldm_x4(a[mf], Ab + SW(a_r + mf * 16, c16 + a_cadd));
            uint32_t b[4][4];
#pragma unroll
            for (int p = 0; p < 4; p++)
                ldm_x4(b[p], Bb + SW(n0 + p * 16 + b_radd, c16 + b_cadd));
#pragma unroll
            for (int mf = 0; mf < 2; mf++)
#pragma unroll
                for (int nf = 0; nf < 8; nf++)
                    mma_bf16(acc[mf][nf], a[mf], b[nf >> 1][(nf & 1) * 2],
                             b[nf >> 1][(nf & 1) * 2 + 1]);
        }
        __syncthreads();
    }

    // ---- Epilogue pass 1: acc -> smem gate planes ----
    float* spre = reinterpret_cast<float*>(smem);          // [4][32][132]
    const int gate = warp >> 1;
#pragma unroll
    for (int mf = 0; mf < 2; mf++) {
        const int row = mf * 16 + (lane >> 2);
#pragma unroll
        for (int nf = 0; nf < 8; nf++) {
            const int col = n0 + nf * 8 + (lane & 3) * 2;
            float* pl = &spre[(size_t)(gate * 32 + row) * 132 + col];
            *reinterpret_cast<float2*>(pl)        = make_float2(acc[mf][nf][0], acc[mf][nf][1]);
            *reinterpret_cast<float2*>(pl + 8*132) = make_float2(acc[mf][nf][2], acc[mf][nf][3]);
        }
    }
    __syncthreads();

    // ---- Epilogue pass 2: cell update ----
    __nv_bfloat16* shT = reinterpret_cast<__nv_bfloat16*>(smem + 4 * 32 * 132 * 4); // [128][34]
    {
        const int hl = tid >> 3;
        const int bs = (tid & 7) * 16;
        const int h = hblk * 32 + hl;
        float q[4][3];
#pragma unroll
        for (int g = 0; g < 4; g++)
#pragma unroll
            for (int v = 0; v < 3; v++) q[g][v] = g_Q[(g * VD + v) * HD + h];

        const float* p0 = &spre[(size_t)(0 * 32 + hl) * 132];
        const float* p1 = &spre[(size_t)(1 * 32 + hl) * 132];
        const float* p2 = &spre[(size_t)(2 * 32 + hl) * 132];
        const float* p3 = &spre[(size_t)(3 * 32 + hl) * 132];

#pragma unroll
        for (int j = 0; j < 16; j += 4) {
            const int bl = bs + j;
            const size_t gidx = (size_t)h * BD + b0 + bl;
            float4 cold = *reinterpret_cast<const float4*>(&g_c[gidx]);
            float4 vg = *reinterpret_cast<const float4*>(&p0[bl]);
            float4 vi = *reinterpret_cast<const float4*>(&p1[bl]);
            float4 vf = *reinterpret_cast<const float4*>(&p2[bl]);
            float4 vo = *reinterpret_cast<const float4*>(&p3[bl]);
            int tk[4];
#pragma unroll
            for (int i = 0; i < 4; i++) tk[i] = x[(size_t)(b0 + bl + i) * SD + t];

            float c2[4], h2[4];
            {
                float gg = tanhf(vg.x + qsel(q[0][0], q[0][1], q[0][2], tk[0]));
                float ii = sigm (vi.x + qsel(q[1][0], q[1][1], q[1][2], tk[0]));
                float ff = sigm (vf.x + qsel(q[2][0], q[2][1], q[2][2], tk[0]));
                float oo = sigm (vo.x + qsel(q[3][0], q[3][1], q[3][2], tk[0]));
                c2[0] = gg * ii + cold.x * ff; h2[0] = tanhf(c2[0]) * oo;
            }
            {
                float gg = tanhf(vg.y + qsel(q[0][0], q[0][1], q[0][2], tk[1]));
                float ii = sigm (vi.y + qsel(q[1][0], q[1][1], q[1][2], tk[1]));
                float ff = sigm (vf.y + qsel(q[2][0], q[2][1], q[2][2], tk[1]));
                float oo = sigm (vo.y + qsel(q[3][0], q[3][1], q[3][2], tk[1]));
                c2[1] = gg * ii + cold.y * ff; h2[1] = tanhf(c2[1]) * oo;
            }
            {
                float gg = tanhf(vg.z + qsel(q[0][0], q[0][1], q[0][2], tk[2]));
                float ii = sigm (vi.z + qsel(q[1][0], q[1][1], q[1][2], tk[2]));
                float ff = sigm (vf.z + qsel(q[2][0], q[2][1], q[2][2], tk[2]));
                float oo = sigm (vo.z + qsel(q[3][0], q[3][1], q[3][2], tk[2]));
                c2[2] = gg * ii + cold.z * ff; h2[2] = tanhf(c2[2]) * oo;
            }
            {
                float gg = tanhf(vg.w + qsel(q[0][0], q[0][1], q[0][2], tk[3]));
                float ii = sigm (vi.w + qsel(q[1][0], q[1][1], q[1][2], tk[3]));
                float ff = sigm (vf.w + qsel(q[2][0], q[2][1], q[2][2], tk[3]));
                float oo = sigm (vo.w + qsel(q[3][0], q[3][1], q[3][2], tk[3]));
                c2[3] = gg * ii + cold.w * ff; h2[3] = tanhf(c2[3]) * oo;
            }
            *reinterpret_cast<float4*>(&g_c[gidx]) = make_float4(c2[0], c2[1], c2[2], c2[3]);
#pragma unroll
            for (int i = 0; i < 4; i++)
                shT[(size_t)(bl + i) * 34 + hl] = __float2bfloat16(h2[i]);
        }
    }
    __syncthreads();

    // ---- Epilogue pass 3: transposed bf16 write of h for next step's B operand ----
    {
        const int bl = tid >> 1;
        const int hs = (tid & 1) * 16;
        uint32_t w[8];
#pragma unroll
        for (int i = 0; i < 8; i++) {
            uint32_t lo = (uint32_t)__bfloat16_as_ushort(shT[(size_t)bl * 34 + hs + 2 * i]);
            uint32_t hi = (uint32_t)__bfloat16_as_ushort(shT[(size_t)bl * 34 + hs + 2 * i + 1]);
            w[i] = lo | (hi << 16);
        }
        const size_t o = (size_t)(b0 + bl) * HD + hblk * 32 + hs;
        *reinterpret_cast<uint4*>(&g_hT[o])     = make_uint4(w[0], w[1], w[2], w[3]);
        *reinterpret_cast<uint4*>(&g_hT[o + 8]) = make_uint4(w[4], w[5], w[6], w[7]);
    }
}

// ---------------------------------------------------------------------------
// Final projection p = W_ph @ h + b_p (C=10) + log_softmax. h read from g_hT.
__global__ void proj_logsoftmax(const float* __restrict__ Wph,
                                const float* __restrict__ bp,
                                float* __restrict__ out) {
    int b = blockIdx.x * blockDim.x + threadIdx.x;
    if (b >= BD) return;
    float acc[CD];
#pragma unroll
    for (int c = 0; c < CD; c++) acc[c] = bp[c];
    const __nv_bfloat16* hrow = &g_hT[(size_t)b * HD];
    for (int k = 0; k < HD; k++) {
        float hv = __bfloat162float(hrow[k]);
#pragma unroll
        for (int c = 0; c < CD; c++) acc[c] = fmaf(Wph[c * HD + k], hv, acc[c]);
    }
    float m = acc[0];
#pragma unroll
    for (int c = 1; c < CD; c++) m = fmaxf(m, acc[c]);
    float s = 0.0f;
#pragma unroll
    for (int c = 0; c < CD; c++) s += expf(acc[c] - m);
    float lse = m + logf(s);
#pragma unroll
    for (int c = 0; c < CD; c++) out[b * CD + c] = acc[c] - lse;
}

// ---------------------------------------------------------------------------
extern "C" void kernel_launch(void* const* d_in, const int* in_sizes, int n_in,
                              void* d_out, int out_size) {
    const int*   x    = (const int*)  d_in[0];
    const float* emb  = (const float*)d_in[1];
    const float* W_gx = (const float*)d_in[2];
    const float* W_gh = (const float*)d_in[3];
    const float* b_g  = (const float*)d_in[4];
    const float* W_ix = (const float*)d_in[5];
    const float* W_ih = (const float*)d_in[6];
    const float* b_i  = (const float*)d_in[7];
    const float* W_fx = (const float*)d_in[8];
    const float* W_fh = (const float*)d_in[9];
    const float* b_f  = (const float*)d_in[10];
    const float* W_ox = (const float*)d_in[11];
    const float* W_oh = (const float*)d_in[12];
    const float* b_o  = (const float*)d_in[13];
    const float* W_ph = (const float*)d_in[14];
    const float* b_p  = (const float*)d_in[15];
    const float* h0   = (const float*)d_in[16];
    const float* c0   = (const float*)d_in[17];
    float* out = (float*)d_out;

    cudaFuncSetAttribute(lstm_step, cudaFuncAttributeMaxDynamicSharedMemorySize, SMEM_STEP);

    init_state<<<(HD * BD + 255) / 256, 256>>>(h0, c0);
    prep_weights<<<(32 * 128 * HD / 4 + 255) / 256, 256>>>(W_gh, W_ih, W_fh, W_oh);
    build_Q<<<(4 * VD * HD + 255) / 256, 256>>>(emb, W_gx, b_g, W_ix, b_i,
                                                W_fx, b_f, W_ox, b_o);

    dim3 grid(BD / NB, HD / 32);   // (8, 32)
    for (int t = 0; t < TD; t++)
        lstm_step<<<grid, 256, SMEM_STEP>>>(x, t);

    proj_logsoftmax<<<(BD + 255) / 256, 256>>>(W_ph, b_p, out);
}

// round 5
// speedup vs baseline: 6.7247x; 1.0021x over previous
#include <cuda_runtime.h>
#include <cuda_bf16.h>
#include <math.h>
#include <stdint.h>

// Problem constants: H=1024, B=1024, S=128 (T=127), E=6, V=3, C=10
#define HD   1024
#define BD   1024
#define SD   128
#define TD   127
#define ED   6
#define VD   3
#define CD   10

#define NB   128      // batch cols per block
#define BK   64       // k per chunk
#define NCH  (HD/BK)  // 16 chunks

// ---------------------------------------------------------------------------
// Static device scratch (no allocations allowed).
__device__ __nv_bfloat16 g_Wr[32u * 128 * HD];  // rearranged weights: [hblk][gate*32+hl][k]
__device__ __nv_bfloat16 g_hT[BD * HD];         // h transposed bf16 [b][h] (B operand)
__device__ float         g_c[HD * BD];          // cell state [h][b]
__device__ float         g_Q[4 * VD * HD];      // input contribution + bias [gate][v][h]
__device__ int           g_tokT[SD * BD];       // tokens transposed [t][b]

// ---------------------------------------------------------------------------
__device__ __forceinline__ uint32_t smem_u32(const void* p) {
    uint32_t a;
    asm("{ .reg .u64 t; cvta.to.shared.u64 t, %1; cvt.u32.u64 %0, t; }" : "=r"(a) : "l"(p));
    return a;
}

__device__ __forceinline__ void cp16(uint32_t dst, const void* src) {
    asm volatile("cp.async.cg.shared.global [%0], [%1], 16;" :: "r"(dst), "l"(src));
}
__device__ __forceinline__ void cp_commit() {
    asm volatile("cp.async.commit_group;" ::: "memory");
}
template <int N> __device__ __forceinline__ void cp_wait() {
    asm volatile("cp.async.wait_group %0;" :: "n"(N) : "memory");
}

__device__ __forceinline__ void ldm_x4(uint32_t r[4], uint32_t addr) {
    asm volatile("ldmatrix.sync.aligned.m8n8.x4.shared.b16 {%0,%1,%2,%3}, [%4];"
                 : "=r"(r[0]), "=r"(r[1]), "=r"(r[2]), "=r"(r[3]) : "r"(addr));
}

__device__ __forceinline__ void mma_bf16(float c[4], const uint32_t a[4],
                                         const uint32_t b0, const uint32_t b1) {
    asm volatile(
        "mma.sync.aligned.m16n8k16.row.col.f32.bf16.bf16.f32 "
        "{%0,%1,%2,%3}, {%4,%5,%6,%7}, {%8,%9}, {%0,%1,%2,%3};"
        : "+f"(c[0]), "+f"(c[1]), "+f"(c[2]), "+f"(c[3])
        : "r"(a[0]), "r"(a[1]), "r"(a[2]), "r"(a[3]), "r"(b0), "r"(b1));
}

__device__ __forceinline__ float sigm(float v) { return 1.0f / (1.0f + __expf(-v)); }
// Branch-free fast tanh, safe for any finite x: e^{-2|x|} is always finite.
__device__ __forceinline__ float ftanh(float x) {
    float e = __expf(-2.0f * fabsf(x));
    float r = (1.0f - e) / (1.0f + e);
    return copysignf(r, x);
}
__device__ __forceinline__ float qsel(float a, float b, float c, int t) {
    return t == 0 ? a : (t == 1 ? b : c);
}

// Swizzled byte offset inside a 128B-row tile: (r, c16) with c16 in [0,8)
__device__ __forceinline__ uint32_t SW(int r, int c16) {
    return (uint32_t)(r * 128) + ((uint32_t)(c16 << 4) ^ (uint32_t)((r & 7) << 4));
}

// ---------------------------------------------------------------------------
// One-time init kernels
__global__ void init_state(const float* __restrict__ h0, const float* __restrict__ c0,
                           const int* __restrict__ x) {
    int i = blockIdx.x * blockDim.x + threadIdx.x;
    if (i < HD * BD) {
        g_c[i] = c0[i];
        int h = i >> 10, b = i & (BD - 1);
        g_hT[(size_t)b * HD + h] = __float2bfloat16(h0[i]);
    }
    if (i < SD * BD) {
        int t = i >> 10, b = i & (BD - 1);
        g_tokT[(size_t)t * BD + b] = x[(size_t)b * SD + t];
    }
}

// Rearranged bf16 weights: g_Wr[((y*128 + gate*32 + hl))*HD + k] = W_gate[(y*32+hl)*HD + k]
__global__ void prep_weights(const float* __restrict__ W0, const float* __restrict__ W1,
                             const float* __restrict__ W2, const float* __restrict__ W3) {
    size_t e = (size_t)(blockIdx.x * blockDim.x + threadIdx.x) * 4;
    if (e >= 32ull * 128 * HD) return;
    int k = (int)(e & (HD - 1));
    int r = (int)((e >> 10) & 127);
    int y = (int)(e >> 17);
    int gate = r >> 5;
    int h = y * 32 + (r & 31);
    const float* W = gate == 0 ? W0 : gate == 1 ? W1 : gate == 2 ? W2 : W3;
    float4 v = *reinterpret_cast<const float4*>(&W[(size_t)h * HD + k]);
    *reinterpret_cast<__nv_bfloat162*>(&g_Wr[e])     = __floats2bfloat162_rn(v.x, v.y);
    *reinterpret_cast<__nv_bfloat162*>(&g_Wr[e + 2]) = __floats2bfloat162_rn(v.z, v.w);
}

__global__ void build_Q(const float* __restrict__ emb,
                        const float* __restrict__ Wgx, const float* __restrict__ bg,
                        const float* __restrict__ Wix, const float* __restrict__ bi,
                        const float* __restrict__ Wfx, const float* __restrict__ bf,
                        const float* __restrict__ Wox, const float* __restrict__ bo) {
    int i = blockIdx.x * blockDim.x + threadIdx.x;
    if (i >= 4 * VD * HD) return;
    int gate = i / (VD * HD);
    int r = i % (VD * HD);
    int v = r >> 10;
    int h = r & (HD - 1);
    const float* Wx = (gate == 0) ? Wgx : (gate == 1) ? Wix : (gate == 2) ? Wfx : Wox;
    const float* bb = (gate == 0) ? bg  : (gate == 1) ? bi  : (gate == 2) ? bf  : bo;
    float s = bb[h];
#pragma unroll
    for (int e = 0; e < ED; e++) s += Wx[h * ED + e] * emb[v * ED + e];
    g_Q[i] = s;
}

// ---------------------------------------------------------------------------
// Fully fused LSTM step: 4-gate GEMM (bf16 mma.sync) + cell update + transpose.
// Block: m=128 (4 gates x 32 h), n=128 (batch), K=1024.
// Grid: (B/128=8, H/32=32). 256 threads = 8 warps (4 m-groups x 2 n-halves).
// SMEM: mainloop 3 stages x (A 16KB + B 16KB) = 96KB, then reused as
//       spre[4][32][132] f32 (67.6KB) + shT[128][34] bf16 (8.7KB).
#define SMEM_STEP (3 * 32768)

__global__ __launch_bounds__(256, 2) void lstm_step(int t) {
    extern __shared__ char smem[];
    const uint32_t sb = smem_u32(smem);
    const int tid = threadIdx.x;
    const int lane = tid & 31;
    const int warp = tid >> 5;
    const int m0 = (warp >> 1) * 32;    // also: gate = warp>>1
    const int n0 = (warp & 1) * 64;
    const int b0 = blockIdx.x * NB;
    const int hblk = blockIdx.y;

    const __nv_bfloat16* __restrict__ Wblk = &g_Wr[(size_t)hblk * 128 * HD];
    const __nv_bfloat16* __restrict__ Bsrc = &g_hT[(size_t)b0 * HD];

    // cp.async staging: per-thread 4 A units + 4 B units of 16B per stage.
    const int ur = tid >> 3;          // rows ur, ur+32, ur+64, ur+96
    const int uc = tid & 7;           // 16B column
    const uint32_t sw_off = SW(ur, uc);

    // Prefetch stages 0 and 1 (groups 0, 1).
#pragma unroll
    for (int st = 0; st < 2; st++) {
        const int koff = st * BK;
#pragma unroll
        for (int j = 0; j < 4; j++) {
            uint32_t d = sb + st * 32768 + sw_off + j * (32 * 128);
            cp16(d,          &Wblk[(size_t)(ur + j * 32) * HD + koff + uc * 8]);
            cp16(d + 16384,  &Bsrc[(size_t)(ur + j * 32) * HD + koff + uc * 8]);
        }
        cp_commit();
    }

    float acc[2][8][4];
#pragma unroll
    for (int i = 0; i < 2; i++)
#pragma unroll
        for (int j = 0; j < 8; j++)
#pragma unroll
            for (int k = 0; k < 4; k++) acc[i][j][k] = 0.0f;

    // ldmatrix per-lane address components
    const int a_r = m0 + (lane & 15);
    const int a_cadd = lane >> 4;                       // +0/+1 c16
    const int b_radd = (lane & 7) + ((lane & 16) >> 1); // row within 16-row pair group
    const int b_cadd = (lane >> 3) & 1;

    // 3-stage pipeline, ONE barrier per chunk.
    // Per chunk ch: wait(group ch) -> sync -> mma(stage ch%3)
    //               -> issue cp for chunk ch+2 into stage (ch+2)%3 -> commit.
    // The cp target stage (ch+2)%3 == (ch-1)%3 was read at chunk ch-1; every
    // thread passed sync_ch after finishing that mma, so the write is race-free.
#pragma unroll 1
    for (int ch = 0; ch < NCH; ch++) {
        cp_wait<1>();
        __syncthreads();

        const uint32_t Ab = sb + (ch % 3) * 32768;
        const uint32_t Bb = Ab + 16384;
#pragma unroll
        for (int ks = 0; ks < 4; ks++) {
            const int c16 = ks * 2;
            uint32_t a[2][4];
#pragma unroll
            for (int mf = 0; mf < 2; mf++)
                ldm_x4(a[mf], Ab + SW(a_r + mf * 16, c16 + a_cadd));
            uint32_t b[4][4];
#pragma unroll
            for (int p = 0; p < 4; p++)
                ldm_x4(b[p], Bb + SW(n0 + p * 16 + b_radd, c16 + b_cadd));
#pragma unroll
            for (int mf = 0; mf < 2; mf++)
#pragma unroll
                for (int nf = 0; nf < 8; nf++)
                    mma_bf16(acc[mf][nf], a[mf], b[nf >> 1][(nf & 1) * 2],
                             b[nf >> 1][(nf & 1) * 2 + 1]);
        }

        if (ch + 2 < NCH) {
            const int st = (ch + 2) % 3;
            const int koff = (ch + 2) * BK;
#pragma unroll
            for (int j = 0; j < 4; j++) {
                uint32_t d = sb + st * 32768 + sw_off + j * (32 * 128);
                cp16(d,         &Wblk[(size_t)(ur + j * 32) * HD + koff + uc * 8]);
                cp16(d + 16384, &Bsrc[(size_t)(ur + j * 32) * HD + koff + uc * 8]);
            }
        }
        cp_commit();   // empty group near the tail keeps wait<1> accounting exact
    }
    __syncthreads();   // protect stage smem before reuse as epilogue scratch

    // ---- Epilogue pass 1: acc -> smem gate planes ----
    float* spre = reinterpret_cast<float*>(smem);          // [4][32][132]
    const int gate = warp >> 1;
#pragma unroll
    for (int mf = 0; mf < 2; mf++) {
        const int row = mf * 16 + (lane >> 2);
#pragma unroll
        for (int nf = 0; nf < 8; nf++) {
            const int col = n0 + nf * 8 + (lane & 3) * 2;
            float* pl = &spre[(size_t)(gate * 32 + row) * 132 + col];
            *reinterpret_cast<float2*>(pl)         = make_float2(acc[mf][nf][0], acc[mf][nf][1]);
            *reinterpret_cast<float2*>(pl + 8*132) = make_float2(acc[mf][nf][2], acc[mf][nf][3]);
        }
    }
    __syncthreads();

    // ---- Epilogue pass 2: cell update ----
    __nv_bfloat16* shT = reinterpret_cast<__nv_bfloat16*>(smem + 4 * 32 * 132 * 4); // [128][34]
    {
        const int hl = tid >> 3;
        const int bs = (tid & 7) * 16;
        const int h = hblk * 32 + hl;
        float q[4][3];
#pragma unroll
        for (int g = 0; g < 4; g++)
#pragma unroll
            for (int v = 0; v < 3; v++) q[g][v] = g_Q[(g * VD + v) * HD + h];

        const float* p0 = &spre[(size_t)(0 * 32 + hl) * 132];
        const float* p1 = &spre[(size_t)(1 * 32 + hl) * 132];
        const float* p2 = &spre[(size_t)(2 * 32 + hl) * 132];
        const float* p3 = &spre[(size_t)(3 * 32 + hl) * 132];
        const int* __restrict__ tokrow = &g_tokT[(size_t)t * BD + b0];

#pragma unroll
        for (int j = 0; j < 16; j += 4) {
            const int bl = bs + j;
            const size_t gidx = (size_t)h * BD + b0 + bl;
            float4 cold = *reinterpret_cast<const float4*>(&g_c[gidx]);
            float4 vg = *reinterpret_cast<const float4*>(&p0[bl]);
            float4 vi = *reinterpret_cast<const float4*>(&p1[bl]);
            float4 vf = *reinterpret_cast<const float4*>(&p2[bl]);
            float4 vo = *reinterpret_cast<const float4*>(&p3[bl]);
            int4 tkv = *reinterpret_cast<const int4*>(&tokrow[bl]);
            int tk[4] = {tkv.x, tkv.y, tkv.z, tkv.w};

            float c2[4], h2[4];
            {
                float gg = ftanh(vg.x + qsel(q[0][0], q[0][1], q[0][2], tk[0]));
                float ii = sigm (vi.x + qsel(q[1][0], q[1][1], q[1][2], tk[0]));
                float ff = sigm (vf.x + qsel(q[2][0], q[2][1], q[2][2], tk[0]));
                float oo = sigm (vo.x + qsel(q[3][0], q[3][1], q[3][2], tk[0]));
                c2[0] = gg * ii + cold.x * ff; h2[0] = ftanh(c2[0]) * oo;
            }
            {
                float gg = ftanh(vg.y + qsel(q[0][0], q[0][1], q[0][2], tk[1]));
                float ii = sigm (vi.y + qsel(q[1][0], q[1][1], q[1][2], tk[1]));
                float ff = sigm (vf.y + qsel(q[2][0], q[2][1], q[2][2], tk[1]));
                float oo = sigm (vo.y + qsel(q[3][0], q[3][1], q[3][2], tk[1]));
                c2[1] = gg * ii + cold.y * ff; h2[1] = ftanh(c2[1]) * oo;
            }
            {
                float gg = ftanh(vg.z + qsel(q[0][0], q[0][1], q[0][2], tk[2]));
                float ii = sigm (vi.z + qsel(q[1][0], q[1][1], q[1][2], tk[2]));
                float ff = sigm (vf.z + qsel(q[2][0], q[2][1], q[2][2], tk[2]));
                float oo = sigm (vo.z + qsel(q[3][0], q[3][1], q[3][2], tk[2]));
                c2[2] = gg * ii + cold.z * ff; h2[2] = ftanh(c2[2]) * oo;
            }
            {
                float gg = ftanh(vg.w + qsel(q[0][0], q[0][1], q[0][2], tk[3]));
                float ii = sigm (vi.w + qsel(q[1][0], q[1][1], q[1][2], tk[3]));
                float ff = sigm (vf.w + qsel(q[2][0], q[2][1], q[2][2], tk[3]));
                float oo = sigm (vo.w + qsel(q[3][0], q[3][1], q[3][2], tk[3]));
                c2[3] = gg * ii + cold.w * ff; h2[3] = ftanh(c2[3]) * oo;
            }
            *reinterpret_cast<float4*>(&g_c[gidx]) = make_float4(c2[0], c2[1], c2[2], c2[3]);
#pragma unroll
            for (int i = 0; i < 4; i++)
                shT[(size_t)(bl + i) * 34 + hl] = __float2bfloat16(h2[i]);
        }
    }
    __syncthreads();

    // ---- Epilogue pass 3: transposed bf16 write of h for next step's B operand ----
    {
        const int bl = tid >> 1;
        const int hs = (tid & 1) * 16;
        uint32_t w[8];
#pragma unroll
        for (int i = 0; i < 8; i++) {
            uint32_t lo = (uint32_t)__bfloat16_as_ushort(shT[(size_t)bl * 34 + hs + 2 * i]);
            uint32_t hi = (uint32_t)__bfloat16_as_ushort(shT[(size_t)bl * 34 + hs + 2 * i + 1]);
            w[i] = lo | (hi << 16);
        }
        const size_t o = (size_t)(b0 + bl) * HD + hblk * 32 + hs;
        *reinterpret_cast<uint4*>(&g_hT[o])     = make_uint4(w[0], w[1], w[2], w[3]);
        *reinterpret_cast<uint4*>(&g_hT[o + 8]) = make_uint4(w[4], w[5], w[6], w[7]);
    }
}

// ---------------------------------------------------------------------------
// Final projection p = W_ph @ h + b_p (C=10) + log_softmax. h read from g_hT.
__global__ void proj_logsoftmax(const float* __restrict__ Wph,
                                const float* __restrict__ bp,
                                float* __restrict__ out) {
    int b = blockIdx.x * blockDim.x + threadIdx.x;
    if (b >= BD) return;
    float acc[CD];
#pragma unroll
    for (int c = 0; c < CD; c++) acc[c] = bp[c];
    const __nv_bfloat16* hrow = &g_hT[(size_t)b * HD];
    for (int k = 0; k < HD; k++) {
        float hv = __bfloat162float(hrow[k]);
#pragma unroll
        for (int c = 0; c < CD; c++) acc[c] = fmaf(Wph[c * HD + k], hv, acc[c]);
    }
    float m = acc[0];
#pragma unroll
    for (int c = 1; c < CD; c++) m = fmaxf(m, acc[c]);
    float s = 0.0f;
#pragma unroll
    for (int c = 0; c < CD; c++) s += expf(acc[c] - m);
    float lse = m + logf(s);
#pragma unroll
    for (int c = 0; c < CD; c++) out[b * CD + c] = acc[c] - lse;
}

// ---------------------------------------------------------------------------
extern "C" void kernel_launch(void* const* d_in, const int* in_sizes, int n_in,
                              void* d_out, int out_size) {
    const int*   x    = (const int*)  d_in[0];
    const float* emb  = (const float*)d_in[1];
    const float* W_gx = (const float*)d_in[2];
    const float* W_gh = (const float*)d_in[3];
    const float* b_g  = (const float*)d_in[4];
    const float* W_ix = (const float*)d_in[5];
    const float* W_ih = (const float*)d_in[6];
    const float* b_i  = (const float*)d_in[7];
    const float* W_fx = (const float*)d_in[8];
    const float* W_fh = (const float*)d_in[9];
    const float* b_f  = (const float*)d_in[10];
    const float* W_ox = (const float*)d_in[11];
    const float* W_oh = (const float*)d_in[12];
    const float* b_o  = (const float*)d_in[13];
    const float* W_ph = (const float*)d_in[14];
    const float* b_p  = (const float*)d_in[15];
    const float* h0   = (const float*)d_in[16];
    const float* c0   = (const float*)d_in[17];
    float* out = (float*)d_out;

    cudaFuncSetAttribute(lstm_step, cudaFuncAttributeMaxDynamicSharedMemorySize, SMEM_STEP);

    init_state<<<(HD * BD + 255) / 256, 256>>>(h0, c0, x);
    prep_weights<<<(32 * 128 * HD / 4 + 255) / 256, 256>>>(W_gh, W_ih, W_fh, W_oh);
    build_Q<<<(4 * VD * HD + 255) / 256, 256>>>(emb, W_gx, b_g, W_ix, b_i,
                                                W_fx, b_f, W_ox, b_o);

    dim3 grid(BD / NB, HD / 32);   // (8, 32)
    for (int t = 0; t < TD; t++)
        lstm_step<<<grid, 256, SMEM_STEP>>>(t);

    proj_logsoftmax<<<(BD + 255) / 256, 256>>>(W_ph, b_p, out);
}

// round 6
// speedup vs baseline: 6.7391x; 1.0021x over previous
#include <cuda_runtime.h>
#include <cuda_bf16.h>
#include <math.h>
#include <stdint.h>

// Problem constants: H=1024, B=1024, S=128 (T=127), E=6, V=3, C=10
#define HD   1024
#define BD   1024
#define SD   128
#define TD   127
#define ED   6
#define VD   3
#define CD   10

#define NB   128      // batch cols per block

// ---------------------------------------------------------------------------
// Static device scratch (no allocations allowed).
// A in mma.sync fragment layout: frag f = (((hblk*4+mg)*64 + kblk)*2 + mf),
//   frag = 32 lanes x uint4 (a0..a3), 16384 frags * 128 u32 = 8 MB.
__device__ uint32_t g_WF[16384u * 128];
// B (h state) in fragment layout: frag G = nblk*64 + kblk (nblk=b/8, kblk=h/16),
//   frag = 32 lanes x uint2 (b0,b1), 8192 frags * 64 u32 = 2 MB.
__device__ uint32_t g_hF[8192u * 64];
__device__ float    g_c[HD * BD];        // cell state [h][b]
__device__ float    g_Q[4 * VD * HD];    // input contribution + bias [gate][v][h]
__device__ int      g_tokT[SD * BD];     // tokens transposed [t][b]

// ---------------------------------------------------------------------------
__device__ __forceinline__ void mma_bf16(float c[4], const uint32_t a[4],
                                         const uint32_t b0, const uint32_t b1) {
    asm volatile(
        "mma.sync.aligned.m16n8k16.row.col.f32.bf16.bf16.f32 "
        "{%0,%1,%2,%3}, {%4,%5,%6,%7}, {%8,%9}, {%0,%1,%2,%3};"
        : "+f"(c[0]), "+f"(c[1]), "+f"(c[2]), "+f"(c[3])
        : "r"(a[0]), "r"(a[1]), "r"(a[2]), "r"(a[3]), "r"(b0), "r"(b1));
}

__device__ __forceinline__ float sigm(float v) { return 1.0f / (1.0f + __expf(-v)); }
__device__ __forceinline__ float ftanh(float x) {
    float e = __expf(-2.0f * fabsf(x));
    float r = (1.0f - e) / (1.0f + e);
    return copysignf(r, x);
}
__device__ __forceinline__ float qsel(float a, float b, float c, int t) {
    return t == 0 ? a : (t == 1 ? b : c);
}

// ---------------------------------------------------------------------------
// One-time init: cell state, tokens (transposed), h0 -> B-fragment layout.
__global__ void init_state(const float* __restrict__ h0, const float* __restrict__ c0,
                           const int* __restrict__ x) {
    int i = blockIdx.x * blockDim.x + threadIdx.x;
    if (i < HD * BD) g_c[i] = c0[i];
    if (i < SD * BD) {
        int t = i >> 10, b = i & (BD - 1);
        g_tokT[(size_t)t * BD + b] = x[(size_t)b * SD + t];
    }
    if (i < 8192 * 64) {    // one u32 of g_hF
        int G = i >> 6, r = i & 63;
        int l = r >> 1, bsel = r & 1;
        int nblk = G >> 6, kblk = G & 63;
        int n = nblk * 8 + (l >> 2);
        int k0 = kblk * 16 + bsel * 8 + (l & 3) * 2;
        __nv_bfloat162 p = __floats2bfloat162_rn(h0[(size_t)k0 * BD + n],
                                                 h0[(size_t)(k0 + 1) * BD + n]);
        g_hF[i] = *reinterpret_cast<uint32_t*>(&p);
    }
}

// Pack weights into A-fragment layout (canonical m16n8k16 row-major A frags).
__global__ void prep_WF(const float* __restrict__ W0, const float* __restrict__ W1,
                        const float* __restrict__ W2, const float* __restrict__ W3) {
    int gid = blockIdx.x * blockDim.x + threadIdx.x;
    if (gid >= 16384 * 32) return;
    int f = gid >> 5, lane = gid & 31;
    int mf = f & 1, kblk = (f >> 1) & 63, mg = (f >> 7) & 3, hblk = f >> 9;
    const float* W = mg == 0 ? W0 : mg == 1 ? W1 : mg == 2 ? W2 : W3;
    int r = lane >> 2, cp = (lane & 3) * 2;
    int hr = hblk * 32 + mf * 16 + r;          // gate = mg; row within gate = mf*16+r
    int kb = kblk * 16 + cp;
    const float* row0 = &W[(size_t)hr * HD];
    const float* row1 = &W[(size_t)(hr + 8) * HD];
    __nv_bfloat162 p0 = __floats2bfloat162_rn(row0[kb],     row0[kb + 1]);
    __nv_bfloat162 p1 = __floats2bfloat162_rn(row1[kb],     row1[kb + 1]);
    __nv_bfloat162 p2 = __floats2bfloat162_rn(row0[kb + 8], row0[kb + 9]);
    __nv_bfloat162 p3 = __floats2bfloat162_rn(row1[kb + 8], row1[kb + 9]);
    uint4 v = make_uint4(*reinterpret_cast<uint32_t*>(&p0),
                         *reinterpret_cast<uint32_t*>(&p1),
                         *reinterpret_cast<uint32_t*>(&p2),
                         *reinterpret_cast<uint32_t*>(&p3));
    reinterpret_cast<uint4*>(g_WF)[(size_t)f * 32 + lane] = v;
}

__global__ void build_Q(const float* __restrict__ emb,
                        const float* __restrict__ Wgx, const float* __restrict__ bg,
                        const float* __restrict__ Wix, const float* __restrict__ bi,
                        const float* __restrict__ Wfx, const float* __restrict__ bf,
                        const float* __restrict__ Wox, const float* __restrict__ bo) {
    int i = blockIdx.x * blockDim.x + threadIdx.x;
    if (i >= 4 * VD * HD) return;
    int gate = i / (VD * HD);
    int r = i % (VD * HD);
    int v = r >> 10;
    int h = r & (HD - 1);
    const float* Wx = (gate == 0) ? Wgx : (gate == 1) ? Wix : (gate == 2) ? Wfx : Wox;
    const float* bb = (gate == 0) ? bg  : (gate == 1) ? bi  : (gate == 2) ? bf  : bo;
    float s = bb[h];
#pragma unroll
    for (int e = 0; e < ED; e++) s += Wx[h * ED + e] * emb[v * ED + e];
    g_Q[i] = s;
}

// ---------------------------------------------------------------------------
// Mainloop helpers: register-direct fragment streaming.
__device__ __forceinline__ void do_load(uint4 a[2], uint2 b[8],
                                        const uint4* __restrict__ A4,
                                        const uint2* __restrict__ B2, int kb) {
    a[0] = __ldg(&A4[(size_t)kb * 64]);
    a[1] = __ldg(&A4[(size_t)kb * 64 + 32]);
#pragma unroll
    for (int nf = 0; nf < 8; nf++)
        b[nf] = __ldg(&B2[(size_t)nf * 2048 + (size_t)kb * 32]);
}

__device__ __forceinline__ void do_mma(float acc[2][8][4], const uint4 a[2],
                                       const uint2 b[8]) {
#pragma unroll
    for (int mf = 0; mf < 2; mf++) {
        uint32_t ar[4] = {a[mf].x, a[mf].y, a[mf].z, a[mf].w};
#pragma unroll
        for (int nf = 0; nf < 8; nf++)
            mma_bf16(acc[mf][nf], ar, b[nf].x, b[nf].y);
    }
}

// ---------------------------------------------------------------------------
// Fully fused LSTM step, no smem in mainloop.
// Block tile m=128 (4 gates x 32 h), n=128 (batch); 8 warps = 4 m-groups x 2 n-halves.
// Epilogue smem: spre[4][32][132] f32 (67584 B) + hF image (8192 B).
#define SMEM_STEP (4 * 32 * 132 * 4 + 16 * 2 * 64 * 4)

__global__ __launch_bounds__(256, 2) void lstm_step(int t) {
    extern __shared__ char smem[];
    const int tid = threadIdx.x, lane = tid & 31, warp = tid >> 5;
    const int mg = warp >> 1, nhalf = warp & 1;
    const int b0 = blockIdx.x * NB;
    const int hblk = blockIdx.y;
    const int nblk0 = (b0 >> 3) + nhalf * 8;

    const uint4* __restrict__ A4 =
        reinterpret_cast<const uint4*>(g_WF) + ((size_t)(hblk * 4 + mg) * 4096 + lane);
    const uint2* __restrict__ B2 =
        reinterpret_cast<const uint2*>(g_hF) + ((size_t)nblk0 * 2048 + lane);

    float acc[2][8][4];
#pragma unroll
    for (int i = 0; i < 2; i++)
#pragma unroll
        for (int j = 0; j < 8; j++)
#pragma unroll
            for (int k = 0; k < 4; k++) acc[i][j][k] = 0.0f;

    uint4 aA[2], aB[2];
    uint2 bA[8], bB[8];
    do_load(aA, bA, A4, B2, 0);

#pragma unroll 1
    for (int kb = 0; kb < 64; kb += 2) {
        do_load(aB, bB, A4, B2, kb + 1);
        do_mma(acc, aA, bA);
        do_load(aA, bA, A4, B2, (kb + 2) & 63);   // wrap on last iter: harmless
        do_mma(acc, aB, bB);
    }

    // ---- Epilogue pass 1: acc -> smem gate planes ----
    float* spre = reinterpret_cast<float*>(smem);          // [4][32][132]
    const int n0 = nhalf * 64;
#pragma unroll
    for (int mf = 0; mf < 2; mf++) {
        const int row = mf * 16 + (lane >> 2);
#pragma unroll
        for (int nf = 0; nf < 8; nf++) {
            const int col = n0 + nf * 8 + (lane & 3) * 2;
            float* pl = &spre[(size_t)(mg * 32 + row) * 132 + col];
            *reinterpret_cast<float2*>(pl)           = make_float2(acc[mf][nf][0], acc[mf][nf][1]);
            *reinterpret_cast<float2*>(pl + 8 * 132) = make_float2(acc[mf][nf][2], acc[mf][nf][3]);
        }
    }
    __syncthreads();

    // ---- Epilogue pass 2: cell update; write h in B-fragment layout to smem ----
    __nv_bfloat16* shF = reinterpret_cast<__nv_bfloat16*>(smem + 4 * 32 * 132 * 4);
    {
        const int hl = tid >> 3;
        const int bs = (tid & 7) * 16;
        const int h = hblk * 32 + hl;
        float q[4][3];
#pragma unroll
        for (int g = 0; g < 4; g++)
#pragma unroll
            for (int v = 0; v < 3; v++) q[g][v] = g_Q[(g * VD + v) * HD + h];

        const float* p0 = &spre[(size_t)(0 * 32 + hl) * 132];
        const float* p1 = &spre[(size_t)(1 * 32 + hl) * 132];
        const float* p2 = &spre[(size_t)(2 * 32 + hl) * 132];
        const float* p3 = &spre[(size_t)(3 * 32 + hl) * 132];
        const int* __restrict__ tokrow = &g_tokT[(size_t)t * BD + b0];

        const int kl = hl >> 4;                 // local k16 block
        const int bsel = (hl >> 3) & 1;         // b0/b1 within frag
        const int lrow = (hl & 7) >> 1;         // lane contribution from k
        const int hhalf = hl & 1;

#pragma unroll
        for (int j = 0; j < 16; j += 4) {
            const int bl = bs + j;
            const size_t gidx = (size_t)h * BD + b0 + bl;
            float4 cold = *reinterpret_cast<const float4*>(&g_c[gidx]);
            float4 vg = *reinterpret_cast<const float4*>(&p0[bl]);
            float4 vi = *reinterpret_cast<const float4*>(&p1[bl]);
            float4 vf = *reinterpret_cast<const float4*>(&p2[bl]);
            float4 vo = *reinterpret_cast<const float4*>(&p3[bl]);
            int4 tkv = *reinterpret_cast<const int4*>(&tokrow[bl]);
            int tk[4] = {tkv.x, tkv.y, tkv.z, tkv.w};

            float c2[4], h2[4];
            float vgx[4] = {vg.x, vg.y, vg.z, vg.w};
            float vix[4] = {vi.x, vi.y, vi.z, vi.w};
            float vfx[4] = {vf.x, vf.y, vf.z, vf.w};
            float vox[4] = {vo.x, vo.y, vo.z, vo.w};
            float cox[4] = {cold.x, cold.y, cold.z, cold.w};
#pragma unroll
            for (int i = 0; i < 4; i++) {
                float gg = ftanh(vgx[i] + qsel(q[0][0], q[0][1], q[0][2], tk[i]));
                float ii = sigm (vix[i] + qsel(q[1][0], q[1][1], q[1][2], tk[i]));
                float ff = sigm (vfx[i] + qsel(q[2][0], q[2][1], q[2][2], tk[i]));
                float oo = sigm (vox[i] + qsel(q[3][0], q[3][1], q[3][2], tk[i]));
                c2[i] = gg * ii + cox[i] * ff;
                h2[i] = ftanh(c2[i]) * oo;
            }
            *reinterpret_cast<float4*>(&g_c[gidx]) = make_float4(c2[0], c2[1], c2[2], c2[3]);
#pragma unroll
            for (int i = 0; i < 4; i++) {
                const int bb = bl + i;
                const int nl = bb >> 3;
                const int l = (bb & 7) * 4 + lrow;
                const int u = ((nl * 2 + kl) * 64) + l * 2 + bsel;
                shF[u * 2 + hhalf] = __float2bfloat16(h2[i]);
            }
        }
    }
    __syncthreads();

    // ---- Epilogue pass 3: copy fragment image to g_hF (coalesced uint2/lane) ----
    {
        const uint32_t* sU = reinterpret_cast<const uint32_t*>(smem + 4 * 32 * 132 * 4);
#pragma unroll
        for (int q2 = 0; q2 < 4; q2++) {
            const int fl = warp * 4 + q2;       // 32 local frags
            const int nl = fl >> 1, kl = fl & 1;
            const size_t G = (size_t)((b0 >> 3) + nl) * 64 + (hblk * 2 + kl);
            uint2 v = *reinterpret_cast<const uint2*>(&sU[fl * 64 + lane * 2]);
            reinterpret_cast<uint2*>(g_hF)[G * 32 + lane] = v;
        }
    }
}

// ---------------------------------------------------------------------------
// Final projection p = W_ph @ h + b_p (C=10) + log_softmax; h read from g_hF.
__global__ void proj_logsoftmax(const float* __restrict__ Wph,
                                const float* __restrict__ bp,
                                float* __restrict__ out) {
    int b = blockIdx.x * blockDim.x + threadIdx.x;
    if (b >= BD) return;
    float acc[CD];
#pragma unroll
    for (int c = 0; c < CD; c++) acc[c] = bp[c];
    const size_t gb = (size_t)(b >> 3) * 64;
    for (int k = 0; k < HD; k += 2) {
        const int kblk = k >> 4, km = k & 15, bsel = km >> 3;
        const int l = (b & 7) * 4 + ((km & 7) >> 1);
        uint32_t v = g_hF[(gb + kblk) * 64 + l * 2 + bsel];
        __nv_bfloat162 p = *reinterpret_cast<__nv_bfloat162*>(&v);
        float hlo = __bfloat162float(p.x);
        float hhi = __bfloat162float(p.y);
#pragma unroll
        for (int c = 0; c < CD; c++)
            acc[c] = fmaf(Wph[c * HD + k], hlo, fmaf(Wph[c * HD + k + 1], hhi, acc[c]));
    }
    float m = acc[0];
#pragma unroll
    for (int c = 1; c < CD; c++) m = fmaxf(m, acc[c]);
    float s = 0.0f;
#pragma unroll
    for (int c = 0; c < CD; c++) s += expf(acc[c] - m);
    float lse = m + logf(s);
#pragma unroll
    for (int c = 0; c < CD; c++) out[b * CD + c] = acc[c] - lse;
}

// ---------------------------------------------------------------------------
extern "C" void kernel_launch(void* const* d_in, const int* in_sizes, int n_in,
                              void* d_out, int out_size) {
    const int*   x    = (const int*)  d_in[0];
    const float* emb  = (const float*)d_in[1];
    const float* W_gx = (const float*)d_in[2];
    const float* W_gh = (const float*)d_in[3];
    const float* b_g  = (const float*)d_in[4];
    const float* W_ix = (const float*)d_in[5];
    const float* W_ih = (const float*)d_in[6];
    const float* b_i  = (const float*)d_in[7];
    const float* W_fx = (const float*)d_in[8];
    const float* W_fh = (const float*)d_in[9];
    const float* b_f  = (const float*)d_in[10];
    const float* W_ox = (const float*)d_in[11];
    const float* W_oh = (const float*)d_in[12];
    const float* b_o  = (const float*)d_in[13];
    const float* W_ph = (const float*)d_in[14];
    const float* b_p  = (const float*)d_in[15];
    const float* h0   = (const float*)d_in[16];
    const float* c0   = (const float*)d_in[17];
    float* out = (float*)d_out;

    cudaFuncSetAttribute(lstm_step, cudaFuncAttributeMaxDynamicSharedMemorySize, SMEM_STEP);

    init_state<<<(HD * BD + 255) / 256, 256>>>(h0, c0, x);
    prep_WF<<<(16384 * 32 + 255) / 256, 256>>>(W_gh, W_ih, W_fh, W_oh);
    build_Q<<<(4 * VD * HD + 255) / 256, 256>>>(emb, W_gx, b_g, W_ix, b_i,
                                                W_fx, b_f, W_ox, b_o);

    dim3 grid(BD / NB, HD / 32);   // (8, 32)
    for (int t = 0; t < TD; t++)
        lstm_step<<<grid, 256, SMEM_STEP>>>(t);

    proj_logsoftmax<<<(BD + 255) / 256, 256>>>(W_ph, b_p, out);
}